// round 17
// baseline (speedup 1.0000x reference)
#include <cuda_runtime.h>
#include <cstdint>

#define BB 4
#define CC 256
#define HH 64
#define WW 96
#define ND 21
#define HW (HH * WW)

// chunk = 8 channels; 32 chunks total
#define NCH 32
#define GSTRIDE (8 * HW)        // global float stride per chunk

// per-buffer geometry (float units); position entry = 8 floats (8 channels)
#define VROW 556                // V row pitch: 139 quads, 139 % 8 == 3 -> conflict-free
#define AOFF 4448               // A region after 8 V rows
#define AROW 384                // A row pitch (48 positions x 8 ch)
#define BUFSZ 5216              // floats per buffer
#define NBUF 8
#define BUFBYTES (BUFSZ * 4)
#define SMEM_BYTES (NBUF * BUFBYTES)    // 166912 B (dynamic, 1 CTA/SM)

static __device__ __forceinline__ void fma2(unsigned long long& acc,
                                            unsigned long long a, unsigned long long b) {
    asm("fma.rn.f32x2 %0, %1, %2, %0;" : "+l"(acc) : "l"(a), "l"(b));
}
static __device__ __forceinline__ float pairsum(unsigned long long v) {
    float lo, hi;
    asm("mov.b64 {%0, %1}, %2;" : "=f"(lo), "=f"(hi) : "l"(v));
    return lo + hi;
}
static __device__ __forceinline__ void cp4(uint32_t sa, const float* g) {
    asm volatile("cp.async.ca.shared.global [%0], [%1], 4;" :: "r"(sa), "l"(g));
}
static __device__ __forceinline__ void cp_commit() {
    asm volatile("cp.async.commit_group;" ::: "memory");
}
template <int N>
static __device__ __forceinline__ void cp_wait() {
    asm volatile("cp.async.wait_group %0;" :: "n"(N) : "memory");
}
static __device__ __forceinline__ uint32_t s2u(const void* p) {
    uint32_t a;
    asm("{ .reg .u64 t; cvta.to.shared.u64 t, %1; cvt.u32.u64 %0, t; }" : "=r"(a) : "l"(p));
    return a;
}

// Grid: (dyg in [0,3), yp in [0,32), bz: b=bz>>1, parity p=bz&1). 768 blocks, 1 CTA/SM.
// Block 384 thr: l=tid&7 (V row), rest=tid>>3: g=rest%16 (3-half pixel group), dxg=rest/16.
// Thread: 3 pixels x=2(3g+kk)+p (kk<3), 7 dx=7dxg+j, rows y0 / y0+2 share V row l.
// Chunk = 8 channels = two channel-quads q=0,1, both streams unrolled for ILP.
// Pipeline (R14-verified cadence): stage k+4,k+5 -> cp_wait<2> -> barrier -> compute k,k+1.
// Reuse distance: staging at iter k overwrites chunk k-4/k-3 buffers, computed two
// iterations earlier with an intervening barrier -> no cross-thread WAR race.
__global__ __launch_bounds__(384, 1)
void corr_kernel(const float* __restrict__ in1, const float* __restrict__ in2,
                 float* __restrict__ out) {
    extern __shared__ __align__(16) float SM[];

    const int dyg = blockIdx.x;
    const int yp  = blockIdx.y;
    const int b   = blockIdx.z >> 1;
    const int p   = blockIdx.z & 1;
    const int y0  = 4 * (yp >> 1) + (yp & 1);
    const uint32_t smu = s2u(SM);

    const int tid = threadIdx.x;
    for (int i = tid; i < NBUF * BUFSZ; i += 384) SM[i] = 0.f;   // halo/OOB stay zero

    // ---- staging roles: thread stages one V position (8 ch); tid<96 also one A position
    const float* gp0;
    int so0 = -1;                 // byte offset within buffer, or -1 (OOB row)
    {
        int m  = tid / 48;        // V row
        int u  = tid - 48 * m;    // interior half-position
        int yy = y0 + 14 * dyg + 2 * m - 20;
        bool v = ((unsigned)yy < (unsigned)HH);
        gp0 = in2 + ((size_t)b * CC) * HW + (v ? yy : 0) * WW + (p + 2 * u);
        so0 = v ? 4 * (m * VROW + (u + 10) * 8) : -1;
    }
    const float* gp1 = in1;
    int so1 = -1;
    if (tid < 96) {
        int yr = tid / 48;        // A row (y0 or y0+2)
        int h  = tid - 48 * yr;
        gp1 = in1 + ((size_t)b * CC) * HW + (y0 + 2 * yr) * WW + (2 * h + p);
        so1 = 4 * (AOFF + yr * AROW + h * 8);
    }

    auto stage = [&](int bsel) {  // one commit group per 8-channel chunk
        uint32_t base = smu + (uint32_t)(bsel * BUFBYTES);
        if (so0 >= 0) {
#pragma unroll
            for (int c = 0; c < 8; c++) cp4(base + so0 + 4 * c, gp0 + c * HW);
        }
        gp0 += GSTRIDE;
        if (so1 >= 0) {
#pragma unroll
            for (int c = 0; c < 8; c++) cp4(base + so1 + 4 * c, gp1 + c * HW);
            gp1 += GSTRIDE;
        }
        cp_commit();
    };

    // ---- compute roles ----
    const int l    = tid & 7;
    const int rest = tid >> 3;
    const int g    = rest & 15;
    const int dxg  = rest >> 4;
    const int pos0 = 3 * g + 7 * dxg;            // 0..59

    unsigned long long aY[21], aZ[21];           // [j*3+kk]
#pragma unroll
    for (int i = 0; i < 21; i++) { aY[i] = 0ull; aZ[i] = 0ull; }

    auto compute = [&](int k) {
        const float* buf = SM + (k & 7) * BUFSZ;
        const float* Vb = buf + l * VROW + pos0 * 8;
        const float* Ab = buf + AOFF + 3 * g * 8;
        ulonglong2 Ay[6], Az[6];                 // [kk*2+q]
#pragma unroll
        for (int kk = 0; kk < 3; kk++) {
#pragma unroll
            for (int q = 0; q < 2; q++) {
                Ay[kk * 2 + q] = *(const ulonglong2*)(Ab + kk * 8 + q * 4);
                Az[kk * 2 + q] = *(const ulonglong2*)(Ab + AROW + kk * 8 + q * 4);
            }
        }
#pragma unroll
        for (int t = 0; t < 9; t++) {
            ulonglong2 V0 = *(const ulonglong2*)(Vb + t * 8);
            ulonglong2 V1 = *(const ulonglong2*)(Vb + t * 8 + 4);
            const int klo = (t > 6) ? (t - 6) : 0;
            const int khi = (t < 2) ? t : 2;
#pragma unroll
            for (int kk = klo; kk <= khi; kk++) {
                const int idx = (t - kk) * 3 + kk;   // j*3+kk
                fma2(aY[idx], Ay[kk * 2].x, V0.x);     fma2(aY[idx], Ay[kk * 2].y, V0.y);
                fma2(aY[idx], Ay[kk * 2 + 1].x, V1.x); fma2(aY[idx], Ay[kk * 2 + 1].y, V1.y);
                fma2(aZ[idx], Az[kk * 2].x, V0.x);     fma2(aZ[idx], Az[kk * 2].y, V0.y);
                fma2(aZ[idx], Az[kk * 2 + 1].x, V1.x); fma2(aZ[idx], Az[kk * 2 + 1].y, V1.y);
            }
        }
    };

    __syncthreads();              // zero-stores complete before any cp.async lands
    stage(0); stage(1); stage(2); stage(3);

#pragma unroll 1
    for (int k = 0; k < NCH; k += 2) {
        if (k + 4 < NCH) {
            stage((k + 4) & 7);
            stage((k + 5) & 7);
            cp_wait<2>();         // chunks <= k+1 complete in this thread
        } else {
            cp_wait<0>();         // tail: drain everything
        }
        __syncthreads();          // cross-thread visibility + WAR protection
        compute(k);
        compute(k + 1);
    }

    // ---- epilogue ----
    const float scale = 1.f / 256.f;
    if (l <= 6) {                 // row y0, dyi = 7dyg+l
        const int dyi = 7 * dyg + l;
        for (int j = 0; j < 7; j++) {
            const int d = dyi * ND + 7 * dxg + j;
            float* op = out + (((size_t)b * ND * ND + d) * HH + y0) * WW + (6 * g + p);
#pragma unroll
            for (int kk = 0; kk < 3; kk++)
                op[2 * kk] = pairsum(aY[j * 3 + kk]) * scale;
        }
    }
    if (l >= 1) {                 // row y0+2, dyi = 7dyg+l-1
        const int dyi = 7 * dyg + l - 1;
        for (int j = 0; j < 7; j++) {
            const int d = dyi * ND + 7 * dxg + j;
            float* op = out + (((size_t)b * ND * ND + d) * HH + (y0 + 2)) * WW + (6 * g + p);
#pragma unroll
            for (int kk = 0; kk < 3; kk++)
                op[2 * kk] = pairsum(aZ[j * 3 + kk]) * scale;
        }
    }
}

extern "C" void kernel_launch(void* const* d_in, const int* in_sizes, int n_in,
                              void* d_out, int out_size) {
    const float* in1 = (const float*)d_in[0];
    const float* in2 = (const float*)d_in[1];
    float* out = (float*)d_out;
    cudaFuncSetAttribute(corr_kernel, cudaFuncAttributeMaxDynamicSharedMemorySize, SMEM_BYTES);
    dim3 grid(3, 32, 8);
    corr_kernel<<<grid, 384, SMEM_BYTES>>>(in1, in2, out);
}